// round 3
// baseline (speedup 1.0000x reference)
#include <cuda_runtime.h>
#include <cuda_bf16.h>
#include <cstdint>

// Precomputed 1/(2*w^2) so the hot kernel never does a per-thread division.
__device__ float g_inv2w2;

__global__ void msb_setup_kernel(const float* __restrict__ width) {
    float w = *width;
    g_inv2w2 = 0.5f / (w * w);
}

// One thread per (i,j) pair.
// Output layout (reference return order): [mask (N*N), rbf (N*N*16)], float32.
__global__ __launch_bounds__(256)
void msb_edge_kernel(const float* __restrict__ pos,
                     const int* __restrict__ batch,   // int32! (JAX x64-disabled)
                     const float* __restrict__ centers,
                     float* __restrict__ out_mask,
                     float* __restrict__ out_rbf,
                     int n)
{
    const int i = blockIdx.y;
    const int j = blockIdx.x * blockDim.x + threadIdx.x;
    if (j >= n) return;

    const size_t pair = (size_t)i * n + j;
    float4* __restrict__ rbf4 = reinterpret_cast<float4*>(out_rbf + pair * 16);

    const int bi = batch[i];
    const int bj = batch[j];

    if ((bi == bj) && (i != j)) {
        // reference: diff = pos[i]-pos[j] + 1e-10 (per component), dist = ||diff||
        float dx = pos[3 * i + 0] - pos[3 * j + 0] + 1e-10f;
        float dy = pos[3 * i + 1] - pos[3 * j + 1] + 1e-10f;
        float dz = pos[3 * i + 2] - pos[3 * j + 2] + 1e-10f;
        float d2 = dx * dx + dy * dy + dz * dz;
        if (d2 < 64.0f) {  // dist < CUTOFF (=8); sqrt is monotone
            const float d   = sqrtf(d2);
            const float inv = g_inv2w2;
            float v[16];
            #pragma unroll
            for (int r = 0; r < 16; ++r) {
                float t = d - __ldg(&centers[r]);
                v[r] = __expf(-t * t * inv);
            }
            rbf4[0] = make_float4(v[0],  v[1],  v[2],  v[3]);
            rbf4[1] = make_float4(v[4],  v[5],  v[6],  v[7]);
            rbf4[2] = make_float4(v[8],  v[9],  v[10], v[11]);
            rbf4[3] = make_float4(v[12], v[13], v[14], v[15]);
            out_mask[pair] = 1.0f;
            return;
        }
    }
    // Invalid pair: mask = 0, rbf = 0 (reference zeroes rbf via mask multiply).
    const float4 z = make_float4(0.f, 0.f, 0.f, 0.f);
    rbf4[0] = z; rbf4[1] = z; rbf4[2] = z; rbf4[3] = z;
    out_mask[pair] = 0.0f;
}

extern "C" void kernel_launch(void* const* d_in, const int* in_sizes, int n_in,
                              void* d_out, int out_size)
{
    const float* pos     = (const float*)d_in[0];
    const int*   batch   = (const int*)d_in[1];
    const float* centers = (const float*)d_in[2];
    const float* width   = (const float*)d_in[3];

    const int n = in_sizes[0] / 3;          // pos is [N,3]
    const size_t nn = (size_t)n * (size_t)n;

    float* out      = (float*)d_out;
    float* out_mask = out;        // [N*N]
    float* out_rbf  = out + nn;   // [N*N*16]

    msb_setup_kernel<<<1, 1>>>(width);

    dim3 block(256, 1, 1);
    dim3 grid((unsigned)((n + 255) / 256), (unsigned)n, 1);
    msb_edge_kernel<<<grid, block>>>(pos, batch, centers, out_mask, out_rbf, n);
}

// round 4
// speedup vs baseline: 1.5635x; 1.5635x over previous
#include <cuda_runtime.h>
#include <cuda_bf16.h>
#include <cstdint>

// Precomputed 1/(2*w^2): one division total, not 4M.
__device__ float g_inv2w2;

__global__ void msb_setup_kernel(const float* __restrict__ width) {
    float w = *width;
    g_inv2w2 = 0.5f / (w * w);
}

// Cooperative mapping: 4 lanes per (i,j) pair, each lane writes one float4
// (4 of the 16 rbf values). Lane t of a warp writes at pair_base*64 + t*16
// bytes -> warp STG.128 is 512B fully contiguous (4 lines, minimal L1
// wavefronts) instead of the previous 64B-strided pattern (16 lines/instr).
// Output layout (reference return order): [mask (N*N), rbf (N*N*16)], fp32.
__global__ __launch_bounds__(256)
void msb_edge_kernel(const float* __restrict__ pos,
                     const int* __restrict__ batch,   // int32
                     const float* __restrict__ centers,
                     float* __restrict__ out_mask,
                     float* __restrict__ out_rbf,
                     int n)
{
    const int i = blockIdx.y;
    const unsigned tid = blockIdx.x * blockDim.x + threadIdx.x; // over n*4 lanes
    const int j     = (int)(tid >> 2);
    const int chunk = (int)(tid & 3);
    if (j >= n) return;

    const size_t pair = (size_t)i * n + j;

    const int bi = batch[i];
    const int bj = batch[j];

    float4 outv = make_float4(0.f, 0.f, 0.f, 0.f);
    float  maskv = 0.0f;

    if ((bi == bj) && (i != j)) {
        // reference: diff = pos[i]-pos[j] + 1e-10 per component; dist = ||diff||
        float dx = pos[3 * i + 0] - pos[3 * j + 0] + 1e-10f;
        float dy = pos[3 * i + 1] - pos[3 * j + 1] + 1e-10f;
        float dz = pos[3 * i + 2] - pos[3 * j + 2] + 1e-10f;
        float d2 = dx * dx + dy * dy + dz * dz;
        if (d2 < 64.0f) {  // dist < CUTOFF(=8); sqrt monotone
            const float d   = sqrtf(d2);
            const float inv = g_inv2w2;
            const int   c0  = chunk * 4;
            float t0 = d - __ldg(&centers[c0 + 0]);
            float t1 = d - __ldg(&centers[c0 + 1]);
            float t2 = d - __ldg(&centers[c0 + 2]);
            float t3 = d - __ldg(&centers[c0 + 3]);
            outv = make_float4(__expf(-t0 * t0 * inv),
                               __expf(-t1 * t1 * inv),
                               __expf(-t2 * t2 * inv),
                               __expf(-t3 * t3 * inv));
            maskv = 1.0f;
        }
    }

    reinterpret_cast<float4*>(out_rbf)[pair * 4 + chunk] = outv;
    if (chunk == 0) out_mask[pair] = maskv;
}

extern "C" void kernel_launch(void* const* d_in, const int* in_sizes, int n_in,
                              void* d_out, int out_size)
{
    const float* pos     = (const float*)d_in[0];
    const int*   batch   = (const int*)d_in[1];
    const float* centers = (const float*)d_in[2];
    const float* width   = (const float*)d_in[3];

    const int n = in_sizes[0] / 3;          // pos is [N,3]
    const size_t nn = (size_t)n * (size_t)n;

    float* out      = (float*)d_out;
    float* out_mask = out;        // [N*N]
    float* out_rbf  = out + nn;   // [N*N*16]

    msb_setup_kernel<<<1, 1>>>(width);

    // 4 lanes per pair: n*4 lanes per row i.
    dim3 block(256, 1, 1);
    dim3 grid((unsigned)((n * 4 + 255) / 256), (unsigned)n, 1);
    msb_edge_kernel<<<grid, block>>>(pos, batch, centers, out_mask, out_rbf, n);
}